// round 11
// baseline (speedup 1.0000x reference)
#include <cuda_runtime.h>
#include <cuda_fp16.h>
#include <stdint.h>
#include <math.h>

#define B_WIN   1024
#define NTOK    64
#define DIMC    512
#define NH      16
#define HD      32
#define M_TOT   (B_WIN * NTOK)           /* 65536 */
#define SCALE_F 0.17677669529663687f     /* 32^-0.5 */
#define L2E_F   1.4426950408889634f
#define QSCALE  (SCALE_F * L2E_F)        /* q pre-scale incl. log2(e) fold */

/* ---------------- static device scratch (no allocation) ------------------ */
__device__ float g_bias[NH * NTOK * NTOK];          /* pre-multiplied by L2E */
__device__ __half g_x[(size_t)M_TOT * DIMC];
__device__ __half g_att[(size_t)M_TOT * DIMC];      /* [b*64+tok][h*32+d] */
__device__ __half g_wq[3 * DIMC * DIMC];
__device__ __half g_wp[DIMC * DIMC];
/* q/k/v fp16, layout [b][h][tok][d]; q scaled by SCALE*L2E */
__device__ __half g_q[(size_t)M_TOT * DIMC];
__device__ __half g_k[(size_t)M_TOT * DIMC];
__device__ __half g_v[(size_t)M_TOT * DIMC];

/* ---------------- portable tensor-core helpers (sm_80+) ------------------ */
__device__ __forceinline__ uint32_t smem_u32(const void* p) {
    return (uint32_t)__cvta_generic_to_shared(p);
}
__device__ __forceinline__ void ldsm4(uint32_t* r, uint32_t addr) {
    asm volatile("ldmatrix.sync.aligned.m8n8.x4.shared.b16 {%0,%1,%2,%3}, [%4];"
        : "=r"(r[0]), "=r"(r[1]), "=r"(r[2]), "=r"(r[3]) : "r"(addr));
}
__device__ __forceinline__ void ldsm4t(uint32_t* r, uint32_t addr) {
    asm volatile("ldmatrix.sync.aligned.m8n8.x4.trans.shared.b16 {%0,%1,%2,%3}, [%4];"
        : "=r"(r[0]), "=r"(r[1]), "=r"(r[2]), "=r"(r[3]) : "r"(addr));
}
__device__ __forceinline__ void mma_f16(float* d, const uint32_t* a, const uint32_t* b) {
    asm volatile("mma.sync.aligned.m16n8k16.row.col.f32.f16.f16.f32 "
        "{%0,%1,%2,%3}, {%4,%5,%6,%7}, {%8,%9}, {%0,%1,%2,%3};"
        : "+f"(d[0]), "+f"(d[1]), "+f"(d[2]), "+f"(d[3])
        : "r"(a[0]), "r"(a[1]), "r"(a[2]), "r"(a[3]), "r"(b[0]), "r"(b[1]));
}
/* fp16-accumulator HMMA: D(h2 pair) = A*B + 0 / + D */
__device__ __forceinline__ void mma_h16_z(uint32_t* d, const uint32_t* a, const uint32_t* b) {
    asm volatile("mma.sync.aligned.m16n8k16.row.col.f16.f16.f16.f16 "
        "{%0,%1}, {%2,%3,%4,%5}, {%6,%7}, {%8,%9};"
        : "=r"(d[0]), "=r"(d[1])
        : "r"(a[0]), "r"(a[1]), "r"(a[2]), "r"(a[3]),
          "r"(b[0]), "r"(b[1]), "r"(0u), "r"(0u));
}
__device__ __forceinline__ void mma_h16(uint32_t* d, const uint32_t* a, const uint32_t* b) {
    asm volatile("mma.sync.aligned.m16n8k16.row.col.f16.f16.f16.f16 "
        "{%0,%1}, {%2,%3,%4,%5}, {%6,%7}, {%0,%1};"
        : "+r"(d[0]), "+r"(d[1])
        : "r"(a[0]), "r"(a[1]), "r"(a[2]), "r"(a[3]), "r"(b[0]), "r"(b[1]));
}
#define CP_ASYNC16(dst, src) \
    asm volatile("cp.async.cg.shared.global [%0], [%1], 16;" :: "r"(dst), "l"(src))
#define CP_COMMIT()  asm volatile("cp.async.commit_group;" ::: "memory")
#define CP_WAIT2()   asm volatile("cp.async.wait_group 2;" ::: "memory")
#define CP_WAIT1()   asm volatile("cp.async.wait_group 1;" ::: "memory")
#define CP_WAIT0()   asm volatile("cp.async.wait_group 0;" ::: "memory")

__device__ __forceinline__ uint32_t pack_h2(float a, float b) {
    __half2 h = __floats2half2_rn(a, b);
    return *(uint32_t*)&h;
}
__device__ __forceinline__ uint32_t ex2_h2(uint32_t t) {
    uint32_t r;
    asm("ex2.approx.f16x2 %0, %1;" : "=r"(r) : "r"(t));
    return r;
}

/* ================= bias table (pre-scaled by log2 e) ===================== */
__global__ void bias_kernel(const float* __restrict__ theta_max,
                            const float* __restrict__ a_p, const float* __restrict__ b_p,
                            const float* __restrict__ a_r, const float* __restrict__ b_r)
{
    int idx = blockIdx.x * 256 + threadIdx.x;
    int h = idx >> 12;
    int ij = idx & 4095;
    int i = ij >> 6, j = ij & 63;
    int dr = (i >> 3) - (j >> 3);
    int dc = (i & 7) - (j & 7);
    int idx_r  = ((dr % 15) + 15) % 15;
    int idx_az = ((dc % 15) + 15) % 15;
    float az = (float)dc * (2.0f * 3.14159265358979323846f / 32.0f);
    float ra = (float)dr * (theta_max[0] / 32.0f);
    float bv = a_p[idx_az * NH + h] * cosf(az) + b_p[idx_az * NH + h] * sinf(az)
             + a_r[idx_r  * NH + h] * cosf(ra) + b_r[idx_r  * NH + h] * sinf(ra);
    g_bias[idx] = bv * L2E_F;
}

/* ================= fp32 -> fp16 convert ================================== */
__global__ void cvt_kernel(const float* __restrict__ src, int which, int n4)
{
    int i = blockIdx.x * 256 + threadIdx.x;
    if (i >= n4) return;
    float4 v = ((const float4*)src)[i];
    uint2 H = make_uint2(pack_h2(v.x, v.y), pack_h2(v.z, v.w));
    __half* hp = (which == 0) ? g_x : ((which == 1) ? g_wq : g_wp);
    ((uint2*)hp)[i] = H;
}

/* ================= mma.sync fp16 GEMM (fp16-accum, K32 promote) ========== */
/* CTA tile 128x128, 8 warps (4m x 2n), warp tile 32x64. 4-stage ring.      */
#define STAGE_B 16384
#define SMEM_TOTAL (4 * STAGE_B)

template<int MODE>
__global__ __launch_bounds__(256, 2) void mma_gemm(const float* __restrict__ bias,
                                                   float* __restrict__ out)
{
    extern __shared__ char smem[];
    const uint32_t sb = smem_u32(smem);
    const int tid = threadIdx.x, wid = tid >> 5, lane = tid & 31;
    const int m0 = blockIdx.y << 7;
    const int n0 = blockIdx.x << 7;
    const int wm = (wid & 3) << 5;
    const int wn = (wid >> 2) << 6;

    const __half* __restrict__ A = (MODE == 0) ? g_x : g_att;
    const __half* __restrict__ W = (MODE == 0) ? g_wq : g_wp;

    float acc[2][8][4];
#pragma unroll
    for (int a = 0; a < 2; a++)
#pragma unroll
        for (int b = 0; b < 8; b++)
#pragma unroll
            for (int c = 0; c < 4; c++) acc[a][b][c] = 0.0f;

    const int c_r0   = tid >> 2,          c_q0 = tid & 3;
    const int c_r1   = (tid + 256) >> 2;
    const int ksl0 = c_q0 >> 1, half0 = c_q0 & 1;
    const uint32_t off0 = 16u * (ksl0 * 256 + c_r0 * 2 + (half0 ^ ((c_r0 >> 2) & 1)));
    const uint32_t off1 = 16u * (ksl0 * 256 + c_r1 * 2 + (half0 ^ ((c_r1 >> 2) & 1)));
    const int kc0 = ksl0 * 16 + half0 * 8;

#define ISSUE(ch) do {                                                         \
    const uint32_t stg = sb + ((ch) & 3) * STAGE_B;                            \
    const int kk = ((ch) << 5) + kc0;                                          \
    size_t a0 = (size_t)(m0 + c_r0) * DIMC + kk;                               \
    size_t a1 = (size_t)(m0 + c_r1) * DIMC + kk;                               \
    size_t b0 = (size_t)(n0 + c_r0) * DIMC + kk;                               \
    size_t b1 = (size_t)(n0 + c_r1) * DIMC + kk;                               \
    CP_ASYNC16(stg + off0,        A + a0);                                     \
    CP_ASYNC16(stg + off1,        A + a1);                                     \
    CP_ASYNC16(stg + 8192 + off0, W + b0);                                     \
    CP_ASYNC16(stg + 8192 + off1, W + b1);                                     \
    CP_COMMIT();                                                               \
} while (0)

    ISSUE(0); ISSUE(1); ISSUE(2);
    const int rloc = lane & 15, hsel = lane >> 4;
    for (int ch = 0; ch < 16; ++ch) {
        if (ch <= 13)      CP_WAIT2();
        else if (ch == 14) CP_WAIT1();
        else               CP_WAIT0();
        __syncthreads();
        if (ch + 3 < 16) ISSUE(ch + 3);
        const uint32_t stg = sb + (ch & 3) * STAGE_B;

        /* A-frags for both K16 steps of this K32 chunk */
        uint32_t ah[2][2][4];
#pragma unroll
        for (int ks = 0; ks < 2; ++ks)
#pragma unroll
            for (int mt = 0; mt < 2; ++mt) {
                int r = wm + mt * 16 + rloc;
                uint32_t off = 16u * (ks * 256 + r * 2 + (hsel ^ ((r >> 2) & 1)));
                ldsm4(ah[ks][mt], stg + off);
            }
#pragma unroll
        for (int g = 0; g < 4; ++g) {
            int r = wn + g * 16 + rloc;
            uint32_t offk0 = 16u * (r * 2 + (hsel ^ ((r >> 2) & 1)));
            uint32_t bh0[4], bh1[4];
            ldsm4(bh0, stg + 8192 + offk0);
            ldsm4(bh1, stg + 8192 + offk0 + 16u * 256);
#pragma unroll
            for (int mt = 0; mt < 2; ++mt) {
#pragma unroll
                for (int nf = 0; nf < 2; ++nf) {
                    uint32_t bb0[2] = {bh0[nf], bh0[nf + 2]};
                    uint32_t bb1[2] = {bh1[nf], bh1[nf + 2]};
                    uint32_t hacc[2];
                    mma_h16_z(hacc, ah[0][mt], bb0);   /* K32 chunk in fp16 */
                    mma_h16  (hacc, ah[1][mt], bb1);
                    float2 lo = __half22float2(*(__half2*)&hacc[0]);
                    float2 hi = __half22float2(*(__half2*)&hacc[1]);
                    float* ac = acc[mt][2 * g + nf];
                    ac[0] += lo.x; ac[1] += lo.y;
                    ac[2] += hi.x; ac[3] += hi.y;
                }
            }
        }
    }
#undef ISSUE

    /* ---- epilogue ---- */
#pragma unroll
    for (int mt = 0; mt < 2; ++mt) {
#pragma unroll
        for (int f = 0; f < 8; ++f) {
            const int n = n0 + wn + (f >> 1) * 16 + (f & 1) * 8 + (lane & 3) * 2;
            const float2 bv = *(const float2*)&bias[n];
#pragma unroll
            for (int hrow = 0; hrow < 2; ++hrow) {
                const int m = m0 + wm + mt * 16 + (lane >> 2) + hrow * 8;
                float vx = acc[mt][f][hrow * 2 + 0] + bv.x;
                float vy = acc[mt][f][hrow * 2 + 1] + bv.y;
                if (MODE == 0) {
                    const int sel = n >> 9;
                    const int h = (n >> 5) & 15, d = n & 31;
                    if (sel == 0) { vx *= QSCALE; vy *= QSCALE; }
                    __half* dst = (sel == 0) ? g_q : ((sel == 1) ? g_k : g_v);
                    size_t base = (((size_t)(m >> 6) * NH + h) * NTOK + (m & 63)) * HD + d;
                    *(uint32_t*)&dst[base] = pack_h2(vx, vy);
                } else {
                    *(float2*)&out[(size_t)m * DIMC + n] = make_float2(vx, vy);
                }
            }
        }
    }
}

/* ================= tensor-core attention (fp16, f16x2 exp, no-max) ====== */
/* q and bias pre-scaled by L2E, so S is already in log2 domain.            */
#define PITCH 80

__global__ __launch_bounds__(256, 2) void attn_mma_kernel()
{
    const int cta = blockIdx.x;           /* 0 .. 8191 */
    const int b = cta >> 3, hp = cta & 7;
    const int tid = threadIdx.x, wid = tid >> 5, lane = tid & 31;
    const int h2 = wid >> 2;
    const int h  = hp * 2 + h2;
    const int m0 = (wid & 3) << 4;

    __shared__ __align__(16) unsigned char qbuf[2][64 * PITCH];
    __shared__ __align__(16) unsigned char kbuf[2][64 * PITCH];
    __shared__ __align__(16) unsigned char vbuf[2][64 * PITCH];

    /* stage q,k,v for both heads: 1536 x 16B chunks, 6 per thread */
    {
        const size_t base0 = ((size_t)b * NH + hp * 2) * (NTOK * HD);
#pragma unroll
        for (int it = 0; it < 6; ++it) {
            int e = tid + it * 256;
            int which = e / 512;
            int e2 = e & 511;
            int hh = e2 >> 8;
            int e3 = e2 & 255;
            int r = e3 >> 2, c = e3 & 3;
            const __half* gsrc = (which == 0) ? g_q : ((which == 1) ? g_k : g_v);
            unsigned char* dbuf = (which == 0) ? &qbuf[hh][0]
                                : ((which == 1) ? &kbuf[hh][0] : &vbuf[hh][0]);
            CP_ASYNC16(smem_u32(dbuf + r * PITCH + c * 16),
                       gsrc + base0 + (size_t)hh * (NTOK * HD) + r * HD + c * 8);
        }
        CP_COMMIT();
        CP_WAIT0();
    }
    __syncthreads();

    const uint32_t qb = smem_u32(&qbuf[h2][0]);
    const uint32_t kb = smem_u32(&kbuf[h2][0]);
    const uint32_t vb = smem_u32(&vbuf[h2][0]);

    const int rA = m0 + (lane >> 2);      /* local token row (frag row) */
    const int cp = (lane & 3) << 1;       /* fragment col pair */

    /* q A-frags via ldsm4: rows m0..m0+15, 2 k-tiles over d=32 */
    uint32_t aq[2][4];
    {
        const int arow = m0 + (lane & 7) + ((lane >> 3) & 1) * 8;
        const uint32_t acol = (lane >> 4) * 16;
#pragma unroll
        for (int kt = 0; kt < 2; ++kt)
            ldsm4(aq[kt], qb + (uint32_t)arow * PITCH + kt * 32 + acol);
    }

    /* S = q k^T (already in log2 domain) */
    float sc[8][4];
#pragma unroll
    for (int nt = 0; nt < 8; ++nt) { sc[nt][0] = sc[nt][1] = sc[nt][2] = sc[nt][3] = 0.0f; }
    {
        const int brow_l = lane & 15;
        const uint32_t bcol = (lane >> 4) * 16;
#pragma unroll
        for (int g = 0; g < 4; ++g) {
            const uint32_t roff = (uint32_t)(g * 16 + brow_l) * PITCH;
#pragma unroll
            for (int kt = 0; kt < 2; ++kt) {
                uint32_t bt[4];
                ldsm4(bt, kb + roff + kt * 32 + bcol);
                uint32_t b0[2] = {bt[0], bt[2]}, b1[2] = {bt[1], bt[3]};
                mma_f16(sc[2 * g],     aq[kt], b0);
                mma_f16(sc[2 * g + 1], aq[kt], b1);
            }
        }
    }

    /* + bias (pre-scaled by L2E) */
    const float* bp = g_bias + (h << 12);
#pragma unroll
    for (int nt = 0; nt < 8; ++nt) {
        float2 bA = *(const float2*)&bp[rA * 64 + nt * 8 + cp];
        float2 bB = *(const float2*)&bp[(rA + 8) * 64 + nt * 8 + cp];
        sc[nt][0] += bA.x; sc[nt][1] += bA.y;
        sc[nt][2] += bB.x; sc[nt][3] += bB.y;
    }

    /* softmax without max-subtraction, exp = ex2 directly, deferred norm */
    uint32_t pe[8][2];
    float sA = 0.0f, sB = 0.0f;
#pragma unroll
    for (int nt = 0; nt < 8; ++nt) {
        pe[nt][0] = ex2_h2(pack_h2(sc[nt][0], sc[nt][1]));
        pe[nt][1] = ex2_h2(pack_h2(sc[nt][2], sc[nt][3]));
        float2 fA = __half22float2(*(__half2*)&pe[nt][0]);
        float2 fB = __half22float2(*(__half2*)&pe[nt][1]);
        sA += fA.x + fA.y;
        sB += fB.x + fB.y;
    }
    sA += __shfl_xor_sync(0xffffffffu, sA, 1);
    sA += __shfl_xor_sync(0xffffffffu, sA, 2);
    sB += __shfl_xor_sync(0xffffffffu, sB, 1);
    sB += __shfl_xor_sync(0xffffffffu, sB, 2);
    const float iA = 1.0f / sA, iB = 1.0f / sB;

    /* O = P V (unnormalized), V via ldmatrix.trans */
    float oc[4][4];
#pragma unroll
    for (int nt = 0; nt < 4; ++nt) { oc[nt][0] = oc[nt][1] = oc[nt][2] = oc[nt][3] = 0.0f; }
    const uint32_t lrow = (lane & 7) + ((lane >> 3) & 1) * 8;
    const uint32_t lcol16 = (lane >> 4);
#pragma unroll
    for (int kt = 0; kt < 4; ++kt) {
        uint32_t pa[4] = {pe[2 * kt][0], pe[2 * kt][1],
                          pe[2 * kt + 1][0], pe[2 * kt + 1][1]};
        uint32_t v0[4], v1[4];
        const uint32_t roff = (uint32_t)((kt * 16 + lrow) * PITCH);
        ldsm4t(v0, vb + roff + lcol16 * 16);
        ldsm4t(v1, vb + roff + (lcol16 + 2) * 16);
        uint32_t bv[4][2] = {{v0[0], v0[1]}, {v0[2], v0[3]},
                             {v1[0], v1[1]}, {v1[2], v1[3]}};
#pragma unroll
        for (int nt = 0; nt < 4; ++nt)
            mma_f16(oc[nt], pa, bv[nt]);
    }

    /* epilogue: normalize rows and write fp16 to g_att */
    const size_t obA = ((size_t)(b * NTOK + rA)) * DIMC + h * HD;
    const size_t obB = obA + (size_t)8 * DIMC;
#pragma unroll
    for (int nt = 0; nt < 4; ++nt) {
        const int d = nt * 8 + cp;
        *(uint32_t*)&g_att[obA + d] = pack_h2(oc[nt][0] * iA, oc[nt][1] * iA);
        *(uint32_t*)&g_att[obB + d] = pack_h2(oc[nt][2] * iB, oc[nt][3] * iB);
    }
}

/* ========================================================================= */
extern "C" void kernel_launch(void* const* d_in, const int* in_sizes, int n_in,
                              void* d_out, int out_size)
{
    (void)in_sizes; (void)n_in; (void)out_size;
    const float* x      = (const float*)d_in[0];
    const float* theta  = (const float*)d_in[1];
    const float* qkv_w  = (const float*)d_in[2];
    const float* qkv_b  = (const float*)d_in[3];
    const float* proj_w = (const float*)d_in[4];
    const float* proj_b = (const float*)d_in[5];
    const float* a_p    = (const float*)d_in[6];
    const float* b_p    = (const float*)d_in[7];
    const float* a_r    = (const float*)d_in[8];
    const float* b_r    = (const float*)d_in[9];
    float* out = (float*)d_out;

    static int smem_set = 0;
    if (!smem_set) {
        cudaFuncSetAttribute(mma_gemm<0>, cudaFuncAttributeMaxDynamicSharedMemorySize, SMEM_TOTAL);
        cudaFuncSetAttribute(mma_gemm<1>, cudaFuncAttributeMaxDynamicSharedMemorySize, SMEM_TOTAL);
        smem_set = 1;
    }

    bias_kernel<<<256, 256>>>(theta, a_p, b_p, a_r, b_r);
    cvt_kernel<<<(M_TOT * DIMC / 4 + 255) / 256, 256>>>(x, 0, M_TOT * DIMC / 4);
    cvt_kernel<<<(3 * DIMC * DIMC / 4 + 255) / 256, 256>>>(qkv_w, 1, 3 * DIMC * DIMC / 4);
    cvt_kernel<<<(DIMC * DIMC / 4 + 255) / 256, 256>>>(proj_w, 2, DIMC * DIMC / 4);
    mma_gemm<0><<<dim3(12, 512), 256, SMEM_TOTAL>>>(qkv_b, nullptr);
    attn_mma_kernel<<<B_WIN * 8, 256>>>();
    mma_gemm<1><<<dim3(4, 512), 256, SMEM_TOTAL>>>(proj_b, out);
}

// round 12
// speedup vs baseline: 1.1584x; 1.1584x over previous
#include <cuda_runtime.h>
#include <cuda_fp16.h>
#include <stdint.h>
#include <math.h>

#define B_WIN   1024
#define NTOK    64
#define DIMC    512
#define NH      16
#define HD      32
#define M_TOT   (B_WIN * NTOK)           /* 65536 */
#define SCALE_F 0.17677669529663687f     /* 32^-0.5 */
#define L2E_F   1.4426950408889634f
#define QSCALE  (SCALE_F * L2E_F)        /* q pre-scale incl. log2(e) fold */

/* ---------------- static device scratch (no allocation) ------------------ */
__device__ uint32_t g_bias_h2[NH * NTOK * 32];      /* fp16x2 pairs, xL2E */
__device__ __half g_x[(size_t)M_TOT * DIMC];
__device__ __half g_att[(size_t)M_TOT * DIMC];      /* [b*64+tok][h*32+d] */
__device__ __half g_wq[3 * DIMC * DIMC];
__device__ __half g_wp[DIMC * DIMC];
/* q/k/v fp16, layout [b][h][tok][d]; q scaled by SCALE*L2E */
__device__ __half g_q[(size_t)M_TOT * DIMC];
__device__ __half g_k[(size_t)M_TOT * DIMC];
__device__ __half g_v[(size_t)M_TOT * DIMC];

/* ---------------- portable tensor-core helpers (sm_80+) ------------------ */
__device__ __forceinline__ uint32_t smem_u32(const void* p) {
    return (uint32_t)__cvta_generic_to_shared(p);
}
__device__ __forceinline__ void ldsm4(uint32_t* r, uint32_t addr) {
    asm volatile("ldmatrix.sync.aligned.m8n8.x4.shared.b16 {%0,%1,%2,%3}, [%4];"
        : "=r"(r[0]), "=r"(r[1]), "=r"(r[2]), "=r"(r[3]) : "r"(addr));
}
__device__ __forceinline__ void ldsm4t(uint32_t* r, uint32_t addr) {
    asm volatile("ldmatrix.sync.aligned.m8n8.x4.trans.shared.b16 {%0,%1,%2,%3}, [%4];"
        : "=r"(r[0]), "=r"(r[1]), "=r"(r[2]), "=r"(r[3]) : "r"(addr));
}
__device__ __forceinline__ void mma_f16(float* d, const uint32_t* a, const uint32_t* b) {
    asm volatile("mma.sync.aligned.m16n8k16.row.col.f32.f16.f16.f32 "
        "{%0,%1,%2,%3}, {%4,%5,%6,%7}, {%8,%9}, {%0,%1,%2,%3};"
        : "+f"(d[0]), "+f"(d[1]), "+f"(d[2]), "+f"(d[3])
        : "r"(a[0]), "r"(a[1]), "r"(a[2]), "r"(a[3]), "r"(b[0]), "r"(b[1]));
}
#define CP_ASYNC16(dst, src) \
    asm volatile("cp.async.cg.shared.global [%0], [%1], 16;" :: "r"(dst), "l"(src))
#define CP_COMMIT()  asm volatile("cp.async.commit_group;" ::: "memory")
#define CP_WAIT2()   asm volatile("cp.async.wait_group 2;" ::: "memory")
#define CP_WAIT1()   asm volatile("cp.async.wait_group 1;" ::: "memory")
#define CP_WAIT0()   asm volatile("cp.async.wait_group 0;" ::: "memory")

__device__ __forceinline__ uint32_t pack_h2(float a, float b) {
    __half2 h = __floats2half2_rn(a, b);
    return *(uint32_t*)&h;
}
__device__ __forceinline__ uint32_t ex2_h2(uint32_t t) {
    uint32_t r;
    asm("ex2.approx.f16x2 %0, %1;" : "=r"(r) : "r"(t));
    return r;
}
__device__ __forceinline__ uint32_t hadd2_u(uint32_t a, uint32_t b) {
    __half2 t = __hadd2(*(__half2*)&a, *(__half2*)&b);
    return *(uint32_t*)&t;
}

/* ================= fused prep: converts + bias table ===================== */
/* blocks [0,32768)        : x cvt        (8388608 uint2)                    */
/* blocks [32768,33536)    : qkv_w cvt    (196608 uint2)                     */
/* blocks [33536,33792)    : proj_w cvt   (65536 uint2)                      */
/* blocks [33792,33920)    : bias fp16x2  (32768 pairs)                      */
__global__ void prep_kernel(const float* __restrict__ x,
                            const float* __restrict__ qkv_w,
                            const float* __restrict__ proj_w,
                            const float* __restrict__ theta_max,
                            const float* __restrict__ a_p, const float* __restrict__ b_p,
                            const float* __restrict__ a_r, const float* __restrict__ b_r)
{
    const int blk = blockIdx.x;
    if (blk < 33792) {
        const float* src;
        __half* dst;
        int i;
        if (blk < 32768)      { src = x;      dst = g_x;  i = blk * 256 + threadIdx.x; }
        else if (blk < 33536) { src = qkv_w;  dst = g_wq; i = (blk - 32768) * 256 + threadIdx.x; }
        else                  { src = proj_w; dst = g_wp; i = (blk - 33536) * 256 + threadIdx.x; }
        float4 v = ((const float4*)src)[i];
        ((uint2*)dst)[i] = make_uint2(pack_h2(v.x, v.y), pack_h2(v.z, v.w));
    } else {
        int i = (blk - 33792) * 256 + threadIdx.x;      /* pair index < 32768 */
        int h = i >> 11;
        int rem = i & 2047;
        int row = rem >> 5, j2 = rem & 31;
        float bv2[2];
#pragma unroll
        for (int t = 0; t < 2; ++t) {
            int j = j2 * 2 + t;
            int dr = (row >> 3) - (j >> 3);
            int dc = (row & 7) - (j & 7);
            int idx_r  = ((dr % 15) + 15) % 15;
            int idx_az = ((dc % 15) + 15) % 15;
            float az = (float)dc * (2.0f * 3.14159265358979323846f / 32.0f);
            float ra = (float)dr * (theta_max[0] / 32.0f);
            bv2[t] = (a_p[idx_az * NH + h] * cosf(az) + b_p[idx_az * NH + h] * sinf(az)
                    + a_r[idx_r  * NH + h] * cosf(ra) + b_r[idx_r  * NH + h] * sinf(ra)) * L2E_F;
        }
        g_bias_h2[i] = pack_h2(bv2[0], bv2[1]);
    }
}

/* ================= mma.sync fp16 GEMM (R9 config: fp32 accum) ============ */
/* CTA tile 128x128, 8 warps (4m x 2n), warp tile 32x64. 4-stage ring.      */
#define STAGE_B 16384
#define SMEM_TOTAL (4 * STAGE_B)

template<int MODE>
__global__ __launch_bounds__(256, 2) void mma_gemm(const float* __restrict__ bias,
                                                   float* __restrict__ out)
{
    extern __shared__ char smem[];
    const uint32_t sb = smem_u32(smem);
    const int tid = threadIdx.x, wid = tid >> 5, lane = tid & 31;
    const int m0 = blockIdx.y << 7;
    const int n0 = blockIdx.x << 7;
    const int wm = (wid & 3) << 5;
    const int wn = (wid >> 2) << 6;

    const __half* __restrict__ A = (MODE == 0) ? g_x : g_att;
    const __half* __restrict__ W = (MODE == 0) ? g_wq : g_wp;

    float acc[2][8][4];
#pragma unroll
    for (int a = 0; a < 2; a++)
#pragma unroll
        for (int b = 0; b < 8; b++)
#pragma unroll
            for (int c = 0; c < 4; c++) acc[a][b][c] = 0.0f;

    const int c_r0   = tid >> 2,          c_q0 = tid & 3;
    const int c_r1   = (tid + 256) >> 2;
    const int ksl0 = c_q0 >> 1, half0 = c_q0 & 1;
    const uint32_t off0 = 16u * (ksl0 * 256 + c_r0 * 2 + (half0 ^ ((c_r0 >> 2) & 1)));
    const uint32_t off1 = 16u * (ksl0 * 256 + c_r1 * 2 + (half0 ^ ((c_r1 >> 2) & 1)));
    const int kc0 = ksl0 * 16 + half0 * 8;

#define ISSUE(ch) do {                                                         \
    const uint32_t stg = sb + ((ch) & 3) * STAGE_B;                            \
    const int kk = ((ch) << 5) + kc0;                                          \
    size_t a0 = (size_t)(m0 + c_r0) * DIMC + kk;                               \
    size_t a1 = (size_t)(m0 + c_r1) * DIMC + kk;                               \
    size_t b0 = (size_t)(n0 + c_r0) * DIMC + kk;                               \
    size_t b1 = (size_t)(n0 + c_r1) * DIMC + kk;                               \
    CP_ASYNC16(stg + off0,        A + a0);                                     \
    CP_ASYNC16(stg + off1,        A + a1);                                     \
    CP_ASYNC16(stg + 8192 + off0, W + b0);                                     \
    CP_ASYNC16(stg + 8192 + off1, W + b1);                                     \
    CP_COMMIT();                                                               \
} while (0)

    ISSUE(0); ISSUE(1); ISSUE(2);
    const int rloc = lane & 15, hsel = lane >> 4;
    for (int ch = 0; ch < 16; ++ch) {
        if (ch <= 13)      CP_WAIT2();
        else if (ch == 14) CP_WAIT1();
        else               CP_WAIT0();
        __syncthreads();
        if (ch + 3 < 16) ISSUE(ch + 3);
        const uint32_t stg = sb + (ch & 3) * STAGE_B;
#pragma unroll
        for (int ks = 0; ks < 2; ++ks) {
            uint32_t ah[2][4];
#pragma unroll
            for (int mt = 0; mt < 2; ++mt) {
                int r = wm + mt * 16 + rloc;
                uint32_t off = 16u * (ks * 256 + r * 2 + (hsel ^ ((r >> 2) & 1)));
                ldsm4(ah[mt], stg + off);
            }
#pragma unroll
            for (int g = 0; g < 4; ++g) {
                int r = wn + g * 16 + rloc;
                uint32_t off = 16u * (ks * 256 + r * 2 + (hsel ^ ((r >> 2) & 1)));
                uint32_t bh[4];
                ldsm4(bh, stg + 8192 + off);
                uint32_t b0h[2] = {bh[0], bh[2]}, b1h[2] = {bh[1], bh[3]};
#pragma unroll
                for (int mt = 0; mt < 2; ++mt) {
                    mma_f16(acc[mt][2 * g],     ah[mt], b0h);
                    mma_f16(acc[mt][2 * g + 1], ah[mt], b1h);
                }
            }
        }
    }
#undef ISSUE

    /* ---- epilogue ---- */
#pragma unroll
    for (int mt = 0; mt < 2; ++mt) {
#pragma unroll
        for (int f = 0; f < 8; ++f) {
            const int n = n0 + wn + (f >> 1) * 16 + (f & 1) * 8 + (lane & 3) * 2;
            const float2 bv = *(const float2*)&bias[n];
#pragma unroll
            for (int hrow = 0; hrow < 2; ++hrow) {
                const int m = m0 + wm + mt * 16 + (lane >> 2) + hrow * 8;
                float vx = acc[mt][f][hrow * 2 + 0] + bv.x;
                float vy = acc[mt][f][hrow * 2 + 1] + bv.y;
                if (MODE == 0) {
                    const int sel = n >> 9;
                    const int h = (n >> 5) & 15, d = n & 31;
                    if (sel == 0) { vx *= QSCALE; vy *= QSCALE; }
                    __half* dst = (sel == 0) ? g_q : ((sel == 1) ? g_k : g_v);
                    size_t base = (((size_t)(m >> 6) * NH + h) * NTOK + (m & 63)) * HD + d;
                    *(uint32_t*)&dst[base] = pack_h2(vx, vy);
                } else {
                    *(float2*)&out[(size_t)m * DIMC + n] = make_float2(vx, vy);
                }
            }
        }
    }
}

/* ================= tensor-core attention (fp16, f16x2 exp, no-max) ====== */
/* q and bias pre-scaled by L2E, so S is already in log2 domain.            */
#define PITCH 80

__global__ __launch_bounds__(256, 2) void attn_mma_kernel()
{
    const int cta = blockIdx.x;           /* 0 .. 8191 */
    const int b = cta >> 3, hp = cta & 7;
    const int tid = threadIdx.x, wid = tid >> 5, lane = tid & 31;
    const int h2 = wid >> 2;
    const int h  = hp * 2 + h2;
    const int m0 = (wid & 3) << 4;

    __shared__ __align__(16) unsigned char qbuf[2][64 * PITCH];
    __shared__ __align__(16) unsigned char kbuf[2][64 * PITCH];
    __shared__ __align__(16) unsigned char vbuf[2][64 * PITCH];

    /* stage q,k,v for both heads: 1536 x 16B chunks, 6 per thread */
    {
        const size_t base0 = ((size_t)b * NH + hp * 2) * (NTOK * HD);
#pragma unroll
        for (int it = 0; it < 6; ++it) {
            int e = tid + it * 256;
            int which = e / 512;
            int e2 = e & 511;
            int hh = e2 >> 8;
            int e3 = e2 & 255;
            int r = e3 >> 2, c = e3 & 3;
            const __half* gsrc = (which == 0) ? g_q : ((which == 1) ? g_k : g_v);
            unsigned char* dbuf = (which == 0) ? &qbuf[hh][0]
                                : ((which == 1) ? &kbuf[hh][0] : &vbuf[hh][0]);
            CP_ASYNC16(smem_u32(dbuf + r * PITCH + c * 16),
                       gsrc + base0 + (size_t)hh * (NTOK * HD) + r * HD + c * 8);
        }
        CP_COMMIT();
        CP_WAIT0();
    }
    __syncthreads();

    const uint32_t qb = smem_u32(&qbuf[h2][0]);
    const uint32_t kb = smem_u32(&kbuf[h2][0]);
    const uint32_t vb = smem_u32(&vbuf[h2][0]);

    const int rA = m0 + (lane >> 2);      /* local token row (frag row) */
    const int cp = (lane & 3) << 1;       /* fragment col pair */

    /* q A-frags via ldsm4: rows m0..m0+15, 2 k-tiles over d=32 */
    uint32_t aq[2][4];
    {
        const int arow = m0 + (lane & 7) + ((lane >> 3) & 1) * 8;
        const uint32_t acol = (lane >> 4) * 16;
#pragma unroll
        for (int kt = 0; kt < 2; ++kt)
            ldsm4(aq[kt], qb + (uint32_t)arow * PITCH + kt * 32 + acol);
    }

    /* S = q k^T (already in log2 domain) */
    float sc[8][4];
#pragma unroll
    for (int nt = 0; nt < 8; ++nt) { sc[nt][0] = sc[nt][1] = sc[nt][2] = sc[nt][3] = 0.0f; }
    {
        const int brow_l = lane & 15;
        const uint32_t bcol = (lane >> 4) * 16;
#pragma unroll
        for (int g = 0; g < 4; ++g) {
            const uint32_t roff = (uint32_t)(g * 16 + brow_l) * PITCH;
#pragma unroll
            for (int kt = 0; kt < 2; ++kt) {
                uint32_t bt[4];
                ldsm4(bt, kb + roff + kt * 32 + bcol);
                uint32_t b0[2] = {bt[0], bt[2]}, b1[2] = {bt[1], bt[3]};
                mma_f16(sc[2 * g],     aq[kt], b0);
                mma_f16(sc[2 * g + 1], aq[kt], b1);
            }
        }
    }

    /* bias (fp16x2, pre-scaled by L2E) added in h2; exp = ex2; deferred norm */
    const uint32_t* bh2 = g_bias_h2 + (h << 11);
    const int bcolp = (cp >> 1);             /* pair column base */
    uint32_t pe[8][2];
    float sA = 0.0f, sB = 0.0f;
#pragma unroll
    for (int nt = 0; nt < 8; ++nt) {
        uint32_t bA = bh2[rA * 32 + nt * 4 + bcolp];
        uint32_t bB = bh2[(rA + 8) * 32 + nt * 4 + bcolp];
        pe[nt][0] = ex2_h2(hadd2_u(pack_h2(sc[nt][0], sc[nt][1]), bA));
        pe[nt][1] = ex2_h2(hadd2_u(pack_h2(sc[nt][2], sc[nt][3]), bB));
        float2 fA = __half22float2(*(__half2*)&pe[nt][0]);
        float2 fB = __half22float2(*(__half2*)&pe[nt][1]);
        sA += fA.x + fA.y;
        sB += fB.x + fB.y;
    }
    sA += __shfl_xor_sync(0xffffffffu, sA, 1);
    sA += __shfl_xor_sync(0xffffffffu, sA, 2);
    sB += __shfl_xor_sync(0xffffffffu, sB, 1);
    sB += __shfl_xor_sync(0xffffffffu, sB, 2);
    const float iA = 1.0f / sA, iB = 1.0f / sB;

    /* O = P V (unnormalized), V via ldmatrix.trans */
    float oc[4][4];
#pragma unroll
    for (int nt = 0; nt < 4; ++nt) { oc[nt][0] = oc[nt][1] = oc[nt][2] = oc[nt][3] = 0.0f; }
    const uint32_t lrow = (lane & 7) + ((lane >> 3) & 1) * 8;
    const uint32_t lcol16 = (lane >> 4);
#pragma unroll
    for (int kt = 0; kt < 4; ++kt) {
        uint32_t pa[4] = {pe[2 * kt][0], pe[2 * kt][1],
                          pe[2 * kt + 1][0], pe[2 * kt + 1][1]};
        uint32_t v0[4], v1[4];
        const uint32_t roff = (uint32_t)((kt * 16 + lrow) * PITCH);
        ldsm4t(v0, vb + roff + lcol16 * 16);
        ldsm4t(v1, vb + roff + (lcol16 + 2) * 16);
        uint32_t bv[4][2] = {{v0[0], v0[1]}, {v0[2], v0[3]},
                             {v1[0], v1[1]}, {v1[2], v1[3]}};
#pragma unroll
        for (int nt = 0; nt < 4; ++nt)
            mma_f16(oc[nt], pa, bv[nt]);
    }

    /* epilogue: normalize rows and write fp16 to g_att */
    const size_t obA = ((size_t)(b * NTOK + rA)) * DIMC + h * HD;
    const size_t obB = obA + (size_t)8 * DIMC;
#pragma unroll
    for (int nt = 0; nt < 4; ++nt) {
        const int d = nt * 8 + cp;
        *(uint32_t*)&g_att[obA + d] = pack_h2(oc[nt][0] * iA, oc[nt][1] * iA);
        *(uint32_t*)&g_att[obB + d] = pack_h2(oc[nt][2] * iB, oc[nt][3] * iB);
    }
}

/* ========================================================================= */
extern "C" void kernel_launch(void* const* d_in, const int* in_sizes, int n_in,
                              void* d_out, int out_size)
{
    (void)in_sizes; (void)n_in; (void)out_size;
    const float* x      = (const float*)d_in[0];
    const float* theta  = (const float*)d_in[1];
    const float* qkv_w  = (const float*)d_in[2];
    const float* qkv_b  = (const float*)d_in[3];
    const float* proj_w = (const float*)d_in[4];
    const float* proj_b = (const float*)d_in[5];
    const float* a_p    = (const float*)d_in[6];
    const float* b_p    = (const float*)d_in[7];
    const float* a_r    = (const float*)d_in[8];
    const float* b_r    = (const float*)d_in[9];
    float* out = (float*)d_out;

    static int smem_set = 0;
    if (!smem_set) {
        cudaFuncSetAttribute(mma_gemm<0>, cudaFuncAttributeMaxDynamicSharedMemorySize, SMEM_TOTAL);
        cudaFuncSetAttribute(mma_gemm<1>, cudaFuncAttributeMaxDynamicSharedMemorySize, SMEM_TOTAL);
        smem_set = 1;
    }

    prep_kernel<<<33920, 256>>>(x, qkv_w, proj_w, theta, a_p, b_p, a_r, b_r);
    mma_gemm<0><<<dim3(12, 512), 256, SMEM_TOTAL>>>(qkv_b, nullptr);
    attn_mma_kernel<<<B_WIN * 8, 256>>>();
    mma_gemm<1><<<dim3(4, 512), 256, SMEM_TOTAL>>>(proj_b, out);
}

// round 13
// speedup vs baseline: 1.1757x; 1.0149x over previous
#include <cuda_runtime.h>
#include <cuda_fp16.h>
#include <stdint.h>
#include <math.h>

#define B_WIN   1024
#define NTOK    64
#define DIMC    512
#define NH      16
#define HD      32
#define M_TOT   (B_WIN * NTOK)           /* 65536 */
#define SCALE_F 0.17677669529663687f     /* 32^-0.5 */
#define L2E_F   1.4426950408889634f
#define QSCALE  (SCALE_F * L2E_F)        /* q pre-scale incl. log2(e) fold */

/* ---------------- static device scratch (no allocation) ------------------ */
__device__ uint32_t g_bias_h2[NH * NTOK * 32];      /* fp16x2 pairs, xL2E */
__device__ __half g_x[(size_t)M_TOT * DIMC];
__device__ __half g_att[(size_t)M_TOT * DIMC];      /* [b*64+tok][h*32+d] */
__device__ __half g_wq[3 * DIMC * DIMC];
__device__ __half g_wp[DIMC * DIMC];
/* q/k/v fp16, layout [b][h][tok][d]; q scaled by SCALE*L2E */
__device__ __half g_q[(size_t)M_TOT * DIMC];
__device__ __half g_k[(size_t)M_TOT * DIMC];
__device__ __half g_v[(size_t)M_TOT * DIMC];

/* ---------------- portable tensor-core helpers (sm_80+) ------------------ */
__device__ __forceinline__ uint32_t smem_u32(const void* p) {
    return (uint32_t)__cvta_generic_to_shared(p);
}
__device__ __forceinline__ void ldsm4(uint32_t* r, uint32_t addr) {
    asm volatile("ldmatrix.sync.aligned.m8n8.x4.shared.b16 {%0,%1,%2,%3}, [%4];"
        : "=r"(r[0]), "=r"(r[1]), "=r"(r[2]), "=r"(r[3]) : "r"(addr));
}
__device__ __forceinline__ void ldsm4t(uint32_t* r, uint32_t addr) {
    asm volatile("ldmatrix.sync.aligned.m8n8.x4.trans.shared.b16 {%0,%1,%2,%3}, [%4];"
        : "=r"(r[0]), "=r"(r[1]), "=r"(r[2]), "=r"(r[3]) : "r"(addr));
}
__device__ __forceinline__ void mma_f16(float* d, const uint32_t* a, const uint32_t* b) {
    asm volatile("mma.sync.aligned.m16n8k16.row.col.f32.f16.f16.f32 "
        "{%0,%1,%2,%3}, {%4,%5,%6,%7}, {%8,%9}, {%0,%1,%2,%3};"
        : "+f"(d[0]), "+f"(d[1]), "+f"(d[2]), "+f"(d[3])
        : "r"(a[0]), "r"(a[1]), "r"(a[2]), "r"(a[3]), "r"(b[0]), "r"(b[1]));
}
#define CP_ASYNC16(dst, src) \
    asm volatile("cp.async.cg.shared.global [%0], [%1], 16;" :: "r"(dst), "l"(src))
#define CP_COMMIT()  asm volatile("cp.async.commit_group;" ::: "memory")
#define CP_WAIT2()   asm volatile("cp.async.wait_group 2;" ::: "memory")
#define CP_WAIT1()   asm volatile("cp.async.wait_group 1;" ::: "memory")
#define CP_WAIT0()   asm volatile("cp.async.wait_group 0;" ::: "memory")

__device__ __forceinline__ uint32_t pack_h2(float a, float b) {
    __half2 h = __floats2half2_rn(a, b);
    return *(uint32_t*)&h;
}
__device__ __forceinline__ uint32_t ex2_h2(uint32_t t) {
    uint32_t r;
    asm("ex2.approx.f16x2 %0, %1;" : "=r"(r) : "r"(t));
    return r;
}
__device__ __forceinline__ uint32_t hadd2_u(uint32_t a, uint32_t b) {
    __half2 t = __hadd2(*(__half2*)&a, *(__half2*)&b);
    return *(uint32_t*)&t;
}

/* ================= fused prep: converts + bias table ===================== */
__global__ void prep_kernel(const float* __restrict__ x,
                            const float* __restrict__ qkv_w,
                            const float* __restrict__ proj_w,
                            const float* __restrict__ theta_max,
                            const float* __restrict__ a_p, const float* __restrict__ b_p,
                            const float* __restrict__ a_r, const float* __restrict__ b_r)
{
    const int blk = blockIdx.x;
    if (blk < 33792) {
        const float* src;
        __half* dst;
        int i;
        if (blk < 32768)      { src = x;      dst = g_x;  i = blk * 256 + threadIdx.x; }
        else if (blk < 33536) { src = qkv_w;  dst = g_wq; i = (blk - 32768) * 256 + threadIdx.x; }
        else                  { src = proj_w; dst = g_wp; i = (blk - 33536) * 256 + threadIdx.x; }
        float4 v = ((const float4*)src)[i];
        ((uint2*)dst)[i] = make_uint2(pack_h2(v.x, v.y), pack_h2(v.z, v.w));
    } else {
        int i = (blk - 33792) * 256 + threadIdx.x;      /* pair index < 32768 */
        int h = i >> 11;
        int rem = i & 2047;
        int row = rem >> 5, j2 = rem & 31;
        float bv2[2];
#pragma unroll
        for (int t = 0; t < 2; ++t) {
            int j = j2 * 2 + t;
            int dr = (row >> 3) - (j >> 3);
            int dc = (row & 7) - (j & 7);
            int idx_r  = ((dr % 15) + 15) % 15;
            int idx_az = ((dc % 15) + 15) % 15;
            float az = (float)dc * (2.0f * 3.14159265358979323846f / 32.0f);
            float ra = (float)dr * (theta_max[0] / 32.0f);
            bv2[t] = (a_p[idx_az * NH + h] * cosf(az) + b_p[idx_az * NH + h] * sinf(az)
                    + a_r[idx_r  * NH + h] * cosf(ra) + b_r[idx_r  * NH + h] * sinf(ra)) * L2E_F;
        }
        g_bias_h2[i] = pack_h2(bv2[0], bv2[1]);
    }
}

/* ================= mma.sync fp16 GEMM (hoisted-LDSM inner loop) ========== */
/* CTA tile 128x128, 8 warps (4m x 2n), warp tile 32x64. 4-stage ring.      */
#define STAGE_B 16384
#define SMEM_TOTAL (4 * STAGE_B)

template<int MODE>
__global__ __launch_bounds__(256, 2) void mma_gemm(const float* __restrict__ bias,
                                                   float* __restrict__ out)
{
    extern __shared__ char smem[];
    const uint32_t sb = smem_u32(smem);
    const int tid = threadIdx.x, wid = tid >> 5, lane = tid & 31;
    const int m0 = blockIdx.y << 7;
    const int n0 = blockIdx.x << 7;
    const int wm = (wid & 3) << 5;
    const int wn = (wid >> 2) << 6;

    const __half* __restrict__ A = (MODE == 0) ? g_x : g_att;
    const __half* __restrict__ W = (MODE == 0) ? g_wq : g_wp;

    float acc[2][8][4];
#pragma unroll
    for (int a = 0; a < 2; a++)
#pragma unroll
        for (int b = 0; b < 8; b++)
#pragma unroll
            for (int c = 0; c < 4; c++) acc[a][b][c] = 0.0f;

    const int c_r0   = tid >> 2,          c_q0 = tid & 3;
    const int c_r1   = (tid + 256) >> 2;
    const int ksl0 = c_q0 >> 1, half0 = c_q0 & 1;
    const uint32_t off0 = 16u * (ksl0 * 256 + c_r0 * 2 + (half0 ^ ((c_r0 >> 2) & 1)));
    const uint32_t off1 = 16u * (ksl0 * 256 + c_r1 * 2 + (half0 ^ ((c_r1 >> 2) & 1)));
    const int kc0 = ksl0 * 16 + half0 * 8;

#define ISSUE(ch) do {                                                         \
    const uint32_t stg = sb + ((ch) & 3) * STAGE_B;                            \
    const int kk = ((ch) << 5) + kc0;                                          \
    size_t a0 = (size_t)(m0 + c_r0) * DIMC + kk;                               \
    size_t a1 = (size_t)(m0 + c_r1) * DIMC + kk;                               \
    size_t b0 = (size_t)(n0 + c_r0) * DIMC + kk;                               \
    size_t b1 = (size_t)(n0 + c_r1) * DIMC + kk;                               \
    CP_ASYNC16(stg + off0,        A + a0);                                     \
    CP_ASYNC16(stg + off1,        A + a1);                                     \
    CP_ASYNC16(stg + 8192 + off0, W + b0);                                     \
    CP_ASYNC16(stg + 8192 + off1, W + b1);                                     \
    CP_COMMIT();                                                               \
} while (0)

    ISSUE(0); ISSUE(1); ISSUE(2);
    const int rloc = lane & 15, hsel = lane >> 4;
    /* precomputed ldsm base offsets (row-dependent part) */
    const uint32_t aoffA0 = 16u * ((wm +  0 + rloc) * 2 + (hsel ^ (((wm +  0 + rloc) >> 2) & 1)));
    const uint32_t aoffA1 = 16u * ((wm + 16 + rloc) * 2 + (hsel ^ (((wm + 16 + rloc) >> 2) & 1)));
    uint32_t boff[4];
#pragma unroll
    for (int g = 0; g < 4; ++g) {
        int r = wn + g * 16 + rloc;
        boff[g] = 16u * (r * 2 + (hsel ^ ((r >> 2) & 1)));
    }

    for (int ch = 0; ch < 16; ++ch) {
        if (ch <= 13)      CP_WAIT2();
        else if (ch == 14) CP_WAIT1();
        else               CP_WAIT0();
        __syncthreads();
        if (ch + 3 < 16) ISSUE(ch + 3);
        const uint32_t stg = sb + (ch & 3) * STAGE_B;
#pragma unroll
        for (int ks = 0; ks < 2; ++ks) {
            const uint32_t ko = (uint32_t)(ks * 256 * 16);
            /* hoist ALL fragment loads of this ks-step before any HMMA */
            uint32_t ah[2][4];
            uint32_t bh[4][4];
            ldsm4(ah[0], stg + ko + aoffA0);
            ldsm4(ah[1], stg + ko + aoffA1);
#pragma unroll
            for (int g = 0; g < 4; ++g)
                ldsm4(bh[g], stg + 8192 + ko + boff[g]);
#pragma unroll
            for (int g = 0; g < 4; ++g) {
                uint32_t b0h[2] = {bh[g][0], bh[g][2]}, b1h[2] = {bh[g][1], bh[g][3]};
#pragma unroll
                for (int mt = 0; mt < 2; ++mt) {
                    mma_f16(acc[mt][2 * g],     ah[mt], b0h);
                    mma_f16(acc[mt][2 * g + 1], ah[mt], b1h);
                }
            }
        }
    }
#undef ISSUE

    /* ---- epilogue ---- */
#pragma unroll
    for (int mt = 0; mt < 2; ++mt) {
#pragma unroll
        for (int f = 0; f < 8; ++f) {
            const int n = n0 + wn + (f >> 1) * 16 + (f & 1) * 8 + (lane & 3) * 2;
            const float2 bv = *(const float2*)&bias[n];
#pragma unroll
            for (int hrow = 0; hrow < 2; ++hrow) {
                const int m = m0 + wm + mt * 16 + (lane >> 2) + hrow * 8;
                float vx = acc[mt][f][hrow * 2 + 0] + bv.x;
                float vy = acc[mt][f][hrow * 2 + 1] + bv.y;
                if (MODE == 0) {
                    const int sel = n >> 9;
                    const int h = (n >> 5) & 15, d = n & 31;
                    if (sel == 0) { vx *= QSCALE; vy *= QSCALE; }
                    __half* dst = (sel == 0) ? g_q : ((sel == 1) ? g_k : g_v);
                    size_t base = (((size_t)(m >> 6) * NH + h) * NTOK + (m & 63)) * HD + d;
                    *(uint32_t*)&dst[base] = pack_h2(vx, vy);
                } else {
                    *(float2*)&out[(size_t)m * DIMC + n] = make_float2(vx, vy);
                }
            }
        }
    }
}

/* ================= tensor-core attention (fp16, f16x2 exp, no-max) ====== */
#define PITCH 80

__global__ __launch_bounds__(256, 2) void attn_mma_kernel()
{
    const int cta = blockIdx.x;           /* 0 .. 8191 */
    const int b = cta >> 3, hp = cta & 7;
    const int tid = threadIdx.x, wid = tid >> 5, lane = tid & 31;
    const int h2 = wid >> 2;
    const int h  = hp * 2 + h2;
    const int m0 = (wid & 3) << 4;

    __shared__ __align__(16) unsigned char qbuf[2][64 * PITCH];
    __shared__ __align__(16) unsigned char kbuf[2][64 * PITCH];
    __shared__ __align__(16) unsigned char vbuf[2][64 * PITCH];

    /* stage q,k,v for both heads: 1536 x 16B chunks, 6 per thread */
    {
        const size_t base0 = ((size_t)b * NH + hp * 2) * (NTOK * HD);
#pragma unroll
        for (int it = 0; it < 6; ++it) {
            int e = tid + it * 256;
            int which = e / 512;
            int e2 = e & 511;
            int hh = e2 >> 8;
            int e3 = e2 & 255;
            int r = e3 >> 2, c = e3 & 3;
            const __half* gsrc = (which == 0) ? g_q : ((which == 1) ? g_k : g_v);
            unsigned char* dbuf = (which == 0) ? &qbuf[hh][0]
                                : ((which == 1) ? &kbuf[hh][0] : &vbuf[hh][0]);
            CP_ASYNC16(smem_u32(dbuf + r * PITCH + c * 16),
                       gsrc + base0 + (size_t)hh * (NTOK * HD) + r * HD + c * 8);
        }
        CP_COMMIT();
        CP_WAIT0();
    }
    __syncthreads();

    const uint32_t qb = smem_u32(&qbuf[h2][0]);
    const uint32_t kb = smem_u32(&kbuf[h2][0]);
    const uint32_t vb = smem_u32(&vbuf[h2][0]);

    const int rA = m0 + (lane >> 2);      /* local token row (frag row) */
    const int cp = (lane & 3) << 1;       /* fragment col pair */

    /* q A-frags via ldsm4: rows m0..m0+15, 2 k-tiles over d=32 */
    uint32_t aq[2][4];
    {
        const int arow = m0 + (lane & 7) + ((lane >> 3) & 1) * 8;
        const uint32_t acol = (lane >> 4) * 16;
#pragma unroll
        for (int kt = 0; kt < 2; ++kt)
            ldsm4(aq[kt], qb + (uint32_t)arow * PITCH + kt * 32 + acol);
    }

    /* S = q k^T (already in log2 domain) */
    float sc[8][4];
#pragma unroll
    for (int nt = 0; nt < 8; ++nt) { sc[nt][0] = sc[nt][1] = sc[nt][2] = sc[nt][3] = 0.0f; }
    {
        const int brow_l = lane & 15;
        const uint32_t bcol = (lane >> 4) * 16;
#pragma unroll
        for (int g = 0; g < 4; ++g) {
            const uint32_t roff = (uint32_t)(g * 16 + brow_l) * PITCH;
#pragma unroll
            for (int kt = 0; kt < 2; ++kt) {
                uint32_t bt[4];
                ldsm4(bt, kb + roff + kt * 32 + bcol);
                uint32_t b0[2] = {bt[0], bt[2]}, b1[2] = {bt[1], bt[3]};
                mma_f16(sc[2 * g],     aq[kt], b0);
                mma_f16(sc[2 * g + 1], aq[kt], b1);
            }
        }
    }

    /* bias (fp16x2, pre-scaled by L2E) added in h2; exp = ex2; deferred norm */
    const uint32_t* bh2 = g_bias_h2 + (h << 11);
    const int bcolp = (cp >> 1);             /* pair column base */
    uint32_t pe[8][2];
    float sA = 0.0f, sB = 0.0f;
#pragma unroll
    for (int nt = 0; nt < 8; ++nt) {
        uint32_t bA = bh2[rA * 32 + nt * 4 + bcolp];
        uint32_t bB = bh2[(rA + 8) * 32 + nt * 4 + bcolp];
        pe[nt][0] = ex2_h2(hadd2_u(pack_h2(sc[nt][0], sc[nt][1]), bA));
        pe[nt][1] = ex2_h2(hadd2_u(pack_h2(sc[nt][2], sc[nt][3]), bB));
        float2 fA = __half22float2(*(__half2*)&pe[nt][0]);
        float2 fB = __half22float2(*(__half2*)&pe[nt][1]);
        sA += fA.x + fA.y;
        sB += fB.x + fB.y;
    }
    sA += __shfl_xor_sync(0xffffffffu, sA, 1);
    sA += __shfl_xor_sync(0xffffffffu, sA, 2);
    sB += __shfl_xor_sync(0xffffffffu, sB, 1);
    sB += __shfl_xor_sync(0xffffffffu, sB, 2);
    const float iA = 1.0f / sA, iB = 1.0f / sB;

    /* O = P V (unnormalized), V via ldmatrix.trans */
    float oc[4][4];
#pragma unroll
    for (int nt = 0; nt < 4; ++nt) { oc[nt][0] = oc[nt][1] = oc[nt][2] = oc[nt][3] = 0.0f; }
    const uint32_t lrow = (lane & 7) + ((lane >> 3) & 1) * 8;
    const uint32_t lcol16 = (lane >> 4);
#pragma unroll
    for (int kt = 0; kt < 4; ++kt) {
        uint32_t pa[4] = {pe[2 * kt][0], pe[2 * kt][1],
                          pe[2 * kt + 1][0], pe[2 * kt + 1][1]};
        uint32_t v0[4], v1[4];
        const uint32_t roff = (uint32_t)((kt * 16 + lrow) * PITCH);
        ldsm4t(v0, vb + roff + lcol16 * 16);
        ldsm4t(v1, vb + roff + (lcol16 + 2) * 16);
        uint32_t bv[4][2] = {{v0[0], v0[1]}, {v0[2], v0[3]},
                             {v1[0], v1[1]}, {v1[2], v1[3]}};
#pragma unroll
        for (int nt = 0; nt < 4; ++nt)
            mma_f16(oc[nt], pa, bv[nt]);
    }

    /* epilogue: normalize rows and write fp16 to g_att */
    const size_t obA = ((size_t)(b * NTOK + rA)) * DIMC + h * HD;
    const size_t obB = obA + (size_t)8 * DIMC;
#pragma unroll
    for (int nt = 0; nt < 4; ++nt) {
        const int d = nt * 8 + cp;
        *(uint32_t*)&g_att[obA + d] = pack_h2(oc[nt][0] * iA, oc[nt][1] * iA);
        *(uint32_t*)&g_att[obB + d] = pack_h2(oc[nt][2] * iB, oc[nt][3] * iB);
    }
}

/* ========================================================================= */
extern "C" void kernel_launch(void* const* d_in, const int* in_sizes, int n_in,
                              void* d_out, int out_size)
{
    (void)in_sizes; (void)n_in; (void)out_size;
    const float* x      = (const float*)d_in[0];
    const float* theta  = (const float*)d_in[1];
    const float* qkv_w  = (const float*)d_in[2];
    const float* qkv_b  = (const float*)d_in[3];
    const float* proj_w = (const float*)d_in[4];
    const float* proj_b = (const float*)d_in[5];
    const float* a_p    = (const float*)d_in[6];
    const float* b_p    = (const float*)d_in[7];
    const float* a_r    = (const float*)d_in[8];
    const float* b_r    = (const float*)d_in[9];
    float* out = (float*)d_out;

    static int smem_set = 0;
    if (!smem_set) {
        cudaFuncSetAttribute(mma_gemm<0>, cudaFuncAttributeMaxDynamicSharedMemorySize, SMEM_TOTAL);
        cudaFuncSetAttribute(mma_gemm<1>, cudaFuncAttributeMaxDynamicSharedMemorySize, SMEM_TOTAL);
        smem_set = 1;
    }

    prep_kernel<<<33920, 256>>>(x, qkv_w, proj_w, theta, a_p, b_p, a_r, b_r);
    mma_gemm<0><<<dim3(12, 512), 256, SMEM_TOTAL>>>(qkv_b, nullptr);
    attn_mma_kernel<<<B_WIN * 8, 256>>>();
    mma_gemm<1><<<dim3(4, 512), 256, SMEM_TOTAL>>>(proj_b, out);
}

// round 14
// speedup vs baseline: 1.2446x; 1.0586x over previous
#include <cuda_runtime.h>
#include <cuda_fp16.h>
#include <stdint.h>
#include <math.h>

#define B_WIN   1024
#define NTOK    64
#define DIMC    512
#define NH      16
#define HD      32
#define M_TOT   (B_WIN * NTOK)           /* 65536 */
#define SCALE_F 0.17677669529663687f     /* 32^-0.5 */
#define L2E_F   1.4426950408889634f
#define QSCALE  (SCALE_F * L2E_F)        /* q pre-scale incl. log2(e) fold */

/* ---------------- static device scratch (no allocation) ------------------ */
__device__ uint32_t g_bias_h2[NH * NTOK * 32];      /* fp16x2 pairs, xL2E */
__device__ __half g_x[(size_t)M_TOT * DIMC];
__device__ __half g_att[(size_t)M_TOT * DIMC];      /* [b*64+tok][h*32+d] */
__device__ __half g_wq[3 * DIMC * DIMC];
__device__ __half g_wp[DIMC * DIMC];
/* q/k/v fp16, layout [b][h][tok][d]; q scaled by SCALE*L2E */
__device__ __half g_q[(size_t)M_TOT * DIMC];
__device__ __half g_k[(size_t)M_TOT * DIMC];
__device__ __half g_v[(size_t)M_TOT * DIMC];

/* ---------------- portable tensor-core helpers (sm_80+) ------------------ */
__device__ __forceinline__ uint32_t smem_u32(const void* p) {
    return (uint32_t)__cvta_generic_to_shared(p);
}
__device__ __forceinline__ void ldsm4(uint32_t* r, uint32_t addr) {
    asm volatile("ldmatrix.sync.aligned.m8n8.x4.shared.b16 {%0,%1,%2,%3}, [%4];"
        : "=r"(r[0]), "=r"(r[1]), "=r"(r[2]), "=r"(r[3]) : "r"(addr));
}
__device__ __forceinline__ void ldsm4t(uint32_t* r, uint32_t addr) {
    asm volatile("ldmatrix.sync.aligned.m8n8.x4.trans.shared.b16 {%0,%1,%2,%3}, [%4];"
        : "=r"(r[0]), "=r"(r[1]), "=r"(r[2]), "=r"(r[3]) : "r"(addr));
}
__device__ __forceinline__ void mma_f16(float* d, const uint32_t* a, const uint32_t* b) {
    asm volatile("mma.sync.aligned.m16n8k16.row.col.f32.f16.f16.f32 "
        "{%0,%1,%2,%3}, {%4,%5,%6,%7}, {%8,%9}, {%0,%1,%2,%3};"
        : "+f"(d[0]), "+f"(d[1]), "+f"(d[2]), "+f"(d[3])
        : "r"(a[0]), "r"(a[1]), "r"(a[2]), "r"(a[3]), "r"(b[0]), "r"(b[1]));
}
#define CP_ASYNC16(dst, src) \
    asm volatile("cp.async.cg.shared.global [%0], [%1], 16;" :: "r"(dst), "l"(src))
#define CP_COMMIT()  asm volatile("cp.async.commit_group;" ::: "memory")
#define CP_WAIT2()   asm volatile("cp.async.wait_group 2;" ::: "memory")
#define CP_WAIT1()   asm volatile("cp.async.wait_group 1;" ::: "memory")
#define CP_WAIT0()   asm volatile("cp.async.wait_group 0;" ::: "memory")

__device__ __forceinline__ uint32_t pack_h2(float a, float b) {
    __half2 h = __floats2half2_rn(a, b);
    return *(uint32_t*)&h;
}
__device__ __forceinline__ uint32_t ex2_h2(uint32_t t) {
    uint32_t r;
    asm("ex2.approx.f16x2 %0, %1;" : "=r"(r) : "r"(t));
    return r;
}
__device__ __forceinline__ uint32_t hadd2_u(uint32_t a, uint32_t b) {
    __half2 t = __hadd2(*(__half2*)&a, *(__half2*)&b);
    return *(uint32_t*)&t;
}

/* ================= fused prep: converts + bias table ===================== */
__global__ void prep_kernel(const float* __restrict__ x,
                            const float* __restrict__ qkv_w,
                            const float* __restrict__ proj_w,
                            const float* __restrict__ theta_max,
                            const float* __restrict__ a_p, const float* __restrict__ b_p,
                            const float* __restrict__ a_r, const float* __restrict__ b_r)
{
    const int blk = blockIdx.x;
    if (blk < 33792) {
        const float* src;
        __half* dst;
        int i;
        if (blk < 32768)      { src = x;      dst = g_x;  i = blk * 256 + threadIdx.x; }
        else if (blk < 33536) { src = qkv_w;  dst = g_wq; i = (blk - 32768) * 256 + threadIdx.x; }
        else                  { src = proj_w; dst = g_wp; i = (blk - 33536) * 256 + threadIdx.x; }
        float4 v = ((const float4*)src)[i];
        ((uint2*)dst)[i] = make_uint2(pack_h2(v.x, v.y), pack_h2(v.z, v.w));
    } else {
        int i = (blk - 33792) * 256 + threadIdx.x;      /* pair index < 32768 */
        int h = i >> 11;
        int rem = i & 2047;
        int row = rem >> 5, j2 = rem & 31;
        float bv2[2];
#pragma unroll
        for (int t = 0; t < 2; ++t) {
            int j = j2 * 2 + t;
            int dr = (row >> 3) - (j >> 3);
            int dc = (row & 7) - (j & 7);
            int idx_r  = ((dr % 15) + 15) % 15;
            int idx_az = ((dc % 15) + 15) % 15;
            float az = (float)dc * (2.0f * 3.14159265358979323846f / 32.0f);
            float ra = (float)dr * (theta_max[0] / 32.0f);
            bv2[t] = (a_p[idx_az * NH + h] * cosf(az) + b_p[idx_az * NH + h] * sinf(az)
                    + a_r[idx_r  * NH + h] * cosf(ra) + b_r[idx_r  * NH + h] * sinf(ra)) * L2E_F;
        }
        g_bias_h2[i] = pack_h2(bv2[0], bv2[1]);
    }
}

/* ================= mma.sync fp16 GEMM (512 thr, 32x32 warp tile) ========= */
/* CTA tile 128x128, 16 warps (4m x 4n), warp tile 32x32. 4-stage ring.     */
/* Registers ~64/thread -> 2 CTAs/SM -> 32 warps/SM (2x latency hiding).    */
#define STAGE_B 16384
#define SMEM_TOTAL (4 * STAGE_B)

template<int MODE>
__global__ __launch_bounds__(512, 2) void mma_gemm(const float* __restrict__ bias,
                                                   float* __restrict__ out)
{
    extern __shared__ char smem[];
    const uint32_t sb = smem_u32(smem);
    const int tid = threadIdx.x, wid = tid >> 5, lane = tid & 31;
    const int m0 = blockIdx.y << 7;
    const int n0 = blockIdx.x << 7;
    const int wm = (wid & 3) << 5;          /* warp row offset 0..96 */
    const int wn = (wid >> 2) << 5;         /* warp col offset 0..96 */

    const __half* __restrict__ A = (MODE == 0) ? g_x : g_att;
    const __half* __restrict__ W = (MODE == 0) ? g_wq : g_wp;

    float acc[2][4][4];
#pragma unroll
    for (int a = 0; a < 2; a++)
#pragma unroll
        for (int b = 0; b < 4; b++)
#pragma unroll
            for (int c = 0; c < 4; c++) acc[a][b][c] = 0.0f;

    /* loader: 512 threads, one 16B chunk per operand each */
    const int c_r0 = tid >> 2, c_q0 = tid & 3;
    const int ksl0 = c_q0 >> 1, half0 = c_q0 & 1;
    const uint32_t off0 = 16u * (ksl0 * 256 + c_r0 * 2 + (half0 ^ ((c_r0 >> 2) & 1)));
    const int kc0 = ksl0 * 16 + half0 * 8;

#define ISSUE(ch) do {                                                         \
    const uint32_t stg = sb + ((ch) & 3) * STAGE_B;                            \
    const int kk = ((ch) << 5) + kc0;                                          \
    CP_ASYNC16(stg + off0,        A + (size_t)(m0 + c_r0) * DIMC + kk);        \
    CP_ASYNC16(stg + 8192 + off0, W + (size_t)(n0 + c_r0) * DIMC + kk);        \
    CP_COMMIT();                                                               \
} while (0)

    ISSUE(0); ISSUE(1); ISSUE(2);
    const int rloc = lane & 15, hsel = lane >> 4;
    const uint32_t aoff0 = 16u * ((wm +  0 + rloc) * 2 + (hsel ^ (((wm +  0 + rloc) >> 2) & 1)));
    const uint32_t aoff1 = 16u * ((wm + 16 + rloc) * 2 + (hsel ^ (((wm + 16 + rloc) >> 2) & 1)));
    const uint32_t boff0 = 16u * ((wn +  0 + rloc) * 2 + (hsel ^ (((wn +  0 + rloc) >> 2) & 1)));
    const uint32_t boff1 = 16u * ((wn + 16 + rloc) * 2 + (hsel ^ (((wn + 16 + rloc) >> 2) & 1)));

    for (int ch = 0; ch < 16; ++ch) {
        if (ch <= 13)      CP_WAIT2();
        else if (ch == 14) CP_WAIT1();
        else               CP_WAIT0();
        __syncthreads();
        if (ch + 3 < 16) ISSUE(ch + 3);
        const uint32_t stg = sb + (ch & 3) * STAGE_B;
#pragma unroll
        for (int ks = 0; ks < 2; ++ks) {
            const uint32_t ko = (uint32_t)(ks * 256 * 16);
            uint32_t ah[2][4], bh[2][4];
            ldsm4(ah[0], stg + ko + aoff0);
            ldsm4(ah[1], stg + ko + aoff1);
            ldsm4(bh[0], stg + 8192 + ko + boff0);
            ldsm4(bh[1], stg + 8192 + ko + boff1);
#pragma unroll
            for (int bt = 0; bt < 2; ++bt) {
#pragma unroll
                for (int nf = 0; nf < 2; ++nf) {
                    uint32_t bb[2] = {bh[bt][nf], bh[bt][nf + 2]};
#pragma unroll
                    for (int mt = 0; mt < 2; ++mt)
                        mma_f16(acc[mt][bt * 2 + nf], ah[mt], bb);
                }
            }
        }
    }
#undef ISSUE

    /* ---- epilogue ---- */
#pragma unroll
    for (int mt = 0; mt < 2; ++mt) {
#pragma unroll
        for (int f = 0; f < 4; ++f) {
            const int n = n0 + wn + (f >> 1) * 16 + (f & 1) * 8 + (lane & 3) * 2;
            const float2 bv = *(const float2*)&bias[n];
#pragma unroll
            for (int hrow = 0; hrow < 2; ++hrow) {
                const int m = m0 + wm + mt * 16 + (lane >> 2) + hrow * 8;
                float vx = acc[mt][f][hrow * 2 + 0] + bv.x;
                float vy = acc[mt][f][hrow * 2 + 1] + bv.y;
                if (MODE == 0) {
                    const int sel = n >> 9;
                    const int h = (n >> 5) & 15, d = n & 31;
                    if (sel == 0) { vx *= QSCALE; vy *= QSCALE; }
                    __half* dst = (sel == 0) ? g_q : ((sel == 1) ? g_k : g_v);
                    size_t base = (((size_t)(m >> 6) * NH + h) * NTOK + (m & 63)) * HD + d;
                    *(uint32_t*)&dst[base] = pack_h2(vx, vy);
                } else {
                    *(float2*)&out[(size_t)m * DIMC + n] = make_float2(vx, vy);
                }
            }
        }
    }
}

/* ================= tensor-core attention (fp16, f16x2 exp, no-max) ====== */
#define PITCH 80

__global__ __launch_bounds__(256, 2) void attn_mma_kernel()
{
    const int cta = blockIdx.x;           /* 0 .. 8191 */
    const int b = cta >> 3, hp = cta & 7;
    const int tid = threadIdx.x, wid = tid >> 5, lane = tid & 31;
    const int h2 = wid >> 2;
    const int h  = hp * 2 + h2;
    const int m0 = (wid & 3) << 4;

    __shared__ __align__(16) unsigned char qbuf[2][64 * PITCH];
    __shared__ __align__(16) unsigned char kbuf[2][64 * PITCH];
    __shared__ __align__(16) unsigned char vbuf[2][64 * PITCH];

    /* stage q,k,v for both heads: 1536 x 16B chunks, 6 per thread */
    {
        const size_t base0 = ((size_t)b * NH + hp * 2) * (NTOK * HD);
#pragma unroll
        for (int it = 0; it < 6; ++it) {
            int e = tid + it * 256;
            int which = e / 512;
            int e2 = e & 511;
            int hh = e2 >> 8;
            int e3 = e2 & 255;
            int r = e3 >> 2, c = e3 & 3;
            const __half* gsrc = (which == 0) ? g_q : ((which == 1) ? g_k : g_v);
            unsigned char* dbuf = (which == 0) ? &qbuf[hh][0]
                                : ((which == 1) ? &kbuf[hh][0] : &vbuf[hh][0]);
            CP_ASYNC16(smem_u32(dbuf + r * PITCH + c * 16),
                       gsrc + base0 + (size_t)hh * (NTOK * HD) + r * HD + c * 8);
        }
        CP_COMMIT();
        CP_WAIT0();
    }
    __syncthreads();

    const uint32_t qb = smem_u32(&qbuf[h2][0]);
    const uint32_t kb = smem_u32(&kbuf[h2][0]);
    const uint32_t vb = smem_u32(&vbuf[h2][0]);

    const int rA = m0 + (lane >> 2);      /* local token row (frag row) */
    const int cp = (lane & 3) << 1;       /* fragment col pair */

    /* q A-frags via ldsm4: rows m0..m0+15, 2 k-tiles over d=32 */
    uint32_t aq[2][4];
    {
        const int arow = m0 + (lane & 7) + ((lane >> 3) & 1) * 8;
        const uint32_t acol = (lane >> 4) * 16;
#pragma unroll
        for (int kt = 0; kt < 2; ++kt)
            ldsm4(aq[kt], qb + (uint32_t)arow * PITCH + kt * 32 + acol);
    }

    /* S = q k^T (already in log2 domain) */
    float sc[8][4];
#pragma unroll
    for (int nt = 0; nt < 8; ++nt) { sc[nt][0] = sc[nt][1] = sc[nt][2] = sc[nt][3] = 0.0f; }
    {
        const int brow_l = lane & 15;
        const uint32_t bcol = (lane >> 4) * 16;
#pragma unroll
        for (int g = 0; g < 4; ++g) {
            const uint32_t roff = (uint32_t)(g * 16 + brow_l) * PITCH;
#pragma unroll
            for (int kt = 0; kt < 2; ++kt) {
                uint32_t bt[4];
                ldsm4(bt, kb + roff + kt * 32 + bcol);
                uint32_t b0[2] = {bt[0], bt[2]}, b1[2] = {bt[1], bt[3]};
                mma_f16(sc[2 * g],     aq[kt], b0);
                mma_f16(sc[2 * g + 1], aq[kt], b1);
            }
        }
    }

    /* bias (fp16x2, pre-scaled by L2E) added in h2; exp = ex2; deferred norm */
    const uint32_t* bh2 = g_bias_h2 + (h << 11);
    const int bcolp = (cp >> 1);             /* pair column base */
    uint32_t pe[8][2];
    float sA = 0.0f, sB = 0.0f;
#pragma unroll
    for (int nt = 0; nt < 8; ++nt) {
        uint32_t bA = bh2[rA * 32 + nt * 4 + bcolp];
        uint32_t bB = bh2[(rA + 8) * 32 + nt * 4 + bcolp];
        pe[nt][0] = ex2_h2(hadd2_u(pack_h2(sc[nt][0], sc[nt][1]), bA));
        pe[nt][1] = ex2_h2(hadd2_u(pack_h2(sc[nt][2], sc[nt][3]), bB));
        float2 fA = __half22float2(*(__half2*)&pe[nt][0]);
        float2 fB = __half22float2(*(__half2*)&pe[nt][1]);
        sA += fA.x + fA.y;
        sB += fB.x + fB.y;
    }
    sA += __shfl_xor_sync(0xffffffffu, sA, 1);
    sA += __shfl_xor_sync(0xffffffffu, sA, 2);
    sB += __shfl_xor_sync(0xffffffffu, sB, 1);
    sB += __shfl_xor_sync(0xffffffffu, sB, 2);
    const float iA = 1.0f / sA, iB = 1.0f / sB;

    /* O = P V (unnormalized), V via ldmatrix.trans */
    float oc[4][4];
#pragma unroll
    for (int nt = 0; nt < 4; ++nt) { oc[nt][0] = oc[nt][1] = oc[nt][2] = oc[nt][3] = 0.0f; }
    const uint32_t lrow = (lane & 7) + ((lane >> 3) & 1) * 8;
    const uint32_t lcol16 = (lane >> 4);
#pragma unroll
    for (int kt = 0; kt < 4; ++kt) {
        uint32_t pa[4] = {pe[2 * kt][0], pe[2 * kt][1],
                          pe[2 * kt + 1][0], pe[2 * kt + 1][1]};
        uint32_t v0[4], v1[4];
        const uint32_t roff = (uint32_t)((kt * 16 + lrow) * PITCH);
        ldsm4t(v0, vb + roff + lcol16 * 16);
        ldsm4t(v1, vb + roff + (lcol16 + 2) * 16);
        uint32_t bv[4][2] = {{v0[0], v0[1]}, {v0[2], v0[3]},
                             {v1[0], v1[1]}, {v1[2], v1[3]}};
#pragma unroll
        for (int nt = 0; nt < 4; ++nt)
            mma_f16(oc[nt], pa, bv[nt]);
    }

    /* epilogue: normalize rows and write fp16 to g_att */
    const size_t obA = ((size_t)(b * NTOK + rA)) * DIMC + h * HD;
    const size_t obB = obA + (size_t)8 * DIMC;
#pragma unroll
    for (int nt = 0; nt < 4; ++nt) {
        const int d = nt * 8 + cp;
        *(uint32_t*)&g_att[obA + d] = pack_h2(oc[nt][0] * iA, oc[nt][1] * iA);
        *(uint32_t*)&g_att[obB + d] = pack_h2(oc[nt][2] * iB, oc[nt][3] * iB);
    }
}

/* ========================================================================= */
extern "C" void kernel_launch(void* const* d_in, const int* in_sizes, int n_in,
                              void* d_out, int out_size)
{
    (void)in_sizes; (void)n_in; (void)out_size;
    const float* x      = (const float*)d_in[0];
    const float* theta  = (const float*)d_in[1];
    const float* qkv_w  = (const float*)d_in[2];
    const float* qkv_b  = (const float*)d_in[3];
    const float* proj_w = (const float*)d_in[4];
    const float* proj_b = (const float*)d_in[5];
    const float* a_p    = (const float*)d_in[6];
    const float* b_p    = (const float*)d_in[7];
    const float* a_r    = (const float*)d_in[8];
    const float* b_r    = (const float*)d_in[9];
    float* out = (float*)d_out;

    static int smem_set = 0;
    if (!smem_set) {
        cudaFuncSetAttribute(mma_gemm<0>, cudaFuncAttributeMaxDynamicSharedMemorySize, SMEM_TOTAL);
        cudaFuncSetAttribute(mma_gemm<1>, cudaFuncAttributeMaxDynamicSharedMemorySize, SMEM_TOTAL);
        smem_set = 1;
    }

    prep_kernel<<<33920, 256>>>(x, qkv_w, proj_w, theta, a_p, b_p, a_r, b_r);
    mma_gemm<0><<<dim3(12, 512), 512, SMEM_TOTAL>>>(qkv_b, nullptr);
    attn_mma_kernel<<<B_WIN * 8, 256>>>();
    mma_gemm<1><<<dim3(4, 512), 512, SMEM_TOTAL>>>(proj_b, out);
}